// round 1
// baseline (speedup 1.0000x reference)
#include <cuda_runtime.h>
#include <cstring>

// CliffordLinear as one dense GEMM:
//   out[b, o*8+l] = sum_{i,k} X[b, i*8+k] * Weff[o*8+l, i*8+k] + bias[o*8+l]
//   Weff[n, m] = cayley[j,k,l] * W[o,i,j] with j = k ^ l   (n = o*8+l, m = i*8+k)

#define NB      8
#define CIN     256
#define COUT    256
#define BATCH   8192
#define KDIM    (CIN * NB)     // 2048
#define NDIM    (COUT * NB)    // 2048

#define BM 128
#define BN 128
#define BK 16
#define TM 8
#define TN 8

typedef unsigned long long u64;

__device__ float g_Weff[(size_t)NDIM * KDIM];  // 16 MB scratch (static, allowed)

__global__ void build_weff_kernel(const float* __restrict__ W,
                                  const float* __restrict__ C) {
    int idx = blockIdx.x * blockDim.x + threadIdx.x;
    if (idx >= NDIM * KDIM) return;
    int m = idx % KDIM;          // i*8 + k
    int n = idx / KDIM;          // o*8 + l
    int k = m & 7, i = m >> 3;
    int l = n & 7, o = n >> 3;
    int j = k ^ l;
    float sign = C[(j * 8 + k) * 8 + l];      // cayley[j][k][l]
    g_Weff[idx] = sign * W[(o * CIN + i) * NB + j];
}

__device__ __forceinline__ u64 pack_dup(float x) {
    u64 r;
    asm("mov.b64 %0, {%1, %1};" : "=l"(r) : "f"(x));
    return r;
}

__device__ __forceinline__ void fma2(u64& d, u64 a, u64 b) {
    asm("fma.rn.f32x2 %0, %1, %2, %0;" : "+l"(d) : "l"(a), "l"(b));
}

__device__ __forceinline__ float2 unpack2(u64 v) {
    float2 f;
    memcpy(&f, &v, 8);
    return f;
}

__global__ __launch_bounds__(256, 2)
void clifford_gemm_kernel(const float* __restrict__ A,     // X [BATCH, KDIM]
                          const float* __restrict__ bias,  // [NDIM]
                          float* __restrict__ out) {       // [BATCH, NDIM]
    __shared__ float As[BK][BM];
    __shared__ float Bs[BK][BN];

    const int bx = blockIdx.x;   // M tile (0..63)
    const int by = blockIdx.y;   // N tile (0..15)
    const int tid = threadIdx.x;
    const int tr = tid >> 4;     // 0..15
    const int tc = tid & 15;     // 0..15

    // global-load mapping: 128 rows x 16 cols, float4 per thread, 2 passes
    const int ldRow = tid >> 2;        // 0..63
    const int ldCol = (tid & 3) * 4;   // 0,4,8,12

    const float* Ab = A + (size_t)bx * BM * KDIM;
    const float* Bb = g_Weff + (size_t)by * BN * KDIM;

    // acc[u][p]: u = row index (0..3 -> tr*4.., 4..7 -> 64+tr*4..)
    // p = col pair: 0:(tc*4+0,1) 1:(tc*4+2,3) 2:(64+tc*4+0,1) 3:(64+tc*4+2,3)
    u64 acc[TM][TN / 2];
#pragma unroll
    for (int u = 0; u < TM; u++)
#pragma unroll
        for (int p = 0; p < TN / 2; p++) acc[u][p] = 0ull;

    for (int k0 = 0; k0 < KDIM; k0 += BK) {
#pragma unroll
        for (int r = 0; r < 2; r++) {
            int row = ldRow + r * 64;
            float4 va = *(const float4*)(Ab + (size_t)row * KDIM + k0 + ldCol);
            As[ldCol + 0][row] = va.x;
            As[ldCol + 1][row] = va.y;
            As[ldCol + 2][row] = va.z;
            As[ldCol + 3][row] = va.w;
            float4 vb = *(const float4*)(Bb + (size_t)row * KDIM + k0 + ldCol);
            Bs[ldCol + 0][row] = vb.x;
            Bs[ldCol + 1][row] = vb.y;
            Bs[ldCol + 2][row] = vb.z;
            Bs[ldCol + 3][row] = vb.w;
        }
        __syncthreads();

#pragma unroll
        for (int kk = 0; kk < BK; kk++) {
            // A fragment: rows tr*4..+3 and 64+tr*4..+3 (broadcast across tc)
            float4 a0 = *(const float4*)&As[kk][tr * 4];
            float4 a1 = *(const float4*)&As[kk][64 + tr * 4];
            u64 ra2[TM];
            ra2[0] = pack_dup(a0.x); ra2[1] = pack_dup(a0.y);
            ra2[2] = pack_dup(a0.z); ra2[3] = pack_dup(a0.w);
            ra2[4] = pack_dup(a1.x); ra2[5] = pack_dup(a1.y);
            ra2[6] = pack_dup(a1.z); ra2[7] = pack_dup(a1.w);

            // B fragment: cols tc*4..+3 and 64+tc*4..+3 as packed pairs
            ulonglong2 b0 = *(const ulonglong2*)&Bs[kk][tc * 4];
            ulonglong2 b1 = *(const ulonglong2*)&Bs[kk][64 + tc * 4];
            u64 rb2[4] = {b0.x, b0.y, b1.x, b1.y};

#pragma unroll
            for (int u = 0; u < TM; u++) {
                fma2(acc[u][0], ra2[u], rb2[0]);
                fma2(acc[u][1], ra2[u], rb2[1]);
                fma2(acc[u][2], ra2[u], rb2[2]);
                fma2(acc[u][3], ra2[u], rb2[3]);
            }
        }
        __syncthreads();
    }

    // epilogue: out[grow, gcol..gcol+3] = acc + bias
#pragma unroll
    for (int h = 0; h < 2; h++) {
#pragma unroll
        for (int u = 0; u < 4; u++) {
            int grow = bx * BM + h * 64 + tr * 4 + u;
            float* orow = out + (size_t)grow * NDIM + by * BN;
            const float* brow = bias + by * BN;
#pragma unroll
            for (int hc = 0; hc < 2; hc++) {
                int cbase = hc * 64 + tc * 4;
                float2 p0 = unpack2(acc[h * 4 + u][hc * 2 + 0]);
                float2 p1 = unpack2(acc[h * 4 + u][hc * 2 + 1]);
                float4 bi = *(const float4*)&brow[cbase];
                float4 v;
                v.x = p0.x + bi.x;
                v.y = p0.y + bi.y;
                v.z = p1.x + bi.z;
                v.w = p1.y + bi.w;
                *(float4*)&orow[cbase] = v;
            }
        }
    }
}

extern "C" void kernel_launch(void* const* d_in, const int* in_sizes, int n_in,
                              void* d_out, int out_size) {
    const float* x      = (const float*)d_in[0];  // [8192, 256, 8]
    const float* weight = (const float*)d_in[1];  // [256, 256, 8]
    const float* bias   = (const float*)d_in[2];  // [256, 8]
    const float* cayley = (const float*)d_in[3];  // [8, 8, 8]
    float* out = (float*)d_out;                   // [8192, 256, 8]

    (void)in_sizes; (void)n_in; (void)out_size;

    int total = NDIM * KDIM;
    build_weff_kernel<<<(total + 255) / 256, 256>>>(weight, cayley);

    dim3 grid(BATCH / BM, NDIM / BN);   // (64, 16)
    clifford_gemm_kernel<<<grid, 256>>>(x, bias, out);
}

// round 5
// speedup vs baseline: 1.8008x; 1.8008x over previous
#include <cuda_runtime.h>
#include <cuda_bf16.h>
#include <cstdint>

// CliffordLinear == dense GEMM: out[b,n] = sum_k X[b,k]*Weff[n,k] + bias[n]
//   Weff[o*8+l, i*8+kb] = cayley[kb^l, kb, l] * W[o, i, kb^l]
// fp32 accuracy via bf16 2-term split with warp-level mma.sync (HMMA):
//   acc += Ahi*Bhi + Alo*Bhi + Ahi*Blo   (lo*lo dropped, ~2^-18)

#define NB     8
#define CIN    256
#define BATCH  8192
#define KDIM   2048
#define NDIM   2048

#define BM 128
#define BN 128
#define BK 32
#define KT (KDIM / BK)          // 64 k-tiles
#define STAGES 3

#define ROWB 80                 // 64B data + 16B pad per smem row
#define TENSOR_BYTES (128 * ROWB)               // 10240
#define STAGE_BYTES  (4 * TENSOR_BYTES)         // 40960
#define SMEM_TOTAL   (STAGES * STAGE_BYTES)     // 122880

// ---- scratch (static device arrays; no allocs) ----
__device__ __nv_bfloat16 g_Ahi[(size_t)BATCH * KDIM];
__device__ __nv_bfloat16 g_Alo[(size_t)BATCH * KDIM];
__device__ __nv_bfloat16 g_Bhi[(size_t)NDIM * KDIM];
__device__ __nv_bfloat16 g_Blo[(size_t)NDIM * KDIM];

// ---- conversion kernels ----
__global__ void split_x_kernel(const float* __restrict__ x) {
    size_t i = (size_t)blockIdx.x * blockDim.x + threadIdx.x;  // float4 index
    float4 v = ((const float4*)x)[i];
    __nv_bfloat16 h0 = __float2bfloat16(v.x), h1 = __float2bfloat16(v.y);
    __nv_bfloat16 h2 = __float2bfloat16(v.z), h3 = __float2bfloat16(v.w);
    __nv_bfloat16 l0 = __float2bfloat16(v.x - __bfloat162float(h0));
    __nv_bfloat16 l1 = __float2bfloat16(v.y - __bfloat162float(h1));
    __nv_bfloat16 l2 = __float2bfloat16(v.z - __bfloat162float(h2));
    __nv_bfloat16 l3 = __float2bfloat16(v.w - __bfloat162float(h3));
    ((__nv_bfloat162*)g_Ahi)[i * 2 + 0] = __nv_bfloat162(h0, h1);
    ((__nv_bfloat162*)g_Ahi)[i * 2 + 1] = __nv_bfloat162(h2, h3);
    ((__nv_bfloat162*)g_Alo)[i * 2 + 0] = __nv_bfloat162(l0, l1);
    ((__nv_bfloat162*)g_Alo)[i * 2 + 1] = __nv_bfloat162(l2, l3);
}

__global__ void build_weff_kernel(const float* __restrict__ W,
                                  const float* __restrict__ C) {
    int idx = blockIdx.x * blockDim.x + threadIdx.x;  // n*KDIM + k
    int k = idx & (KDIM - 1);
    int n = idx >> 11;
    int kb = k & 7, i = k >> 3;
    int l = n & 7, o = n >> 3;
    int j = kb ^ l;
    float w = C[(j * 8 + kb) * 8 + l] * W[(o * CIN + i) * NB + j];
    __nv_bfloat16 hi = __float2bfloat16(w);
    __nv_bfloat16 lo = __float2bfloat16(w - __bfloat162float(hi));
    g_Bhi[idx] = hi;
    g_Blo[idx] = lo;
}

// ---- mma / cp.async helpers (all plain sm80-level PTX) ----
__device__ __forceinline__ void mma_bf16(float* c, const uint32_t* a, const uint32_t* b) {
    asm volatile(
        "mma.sync.aligned.m16n8k16.row.col.f32.bf16.bf16.f32 "
        "{%0,%1,%2,%3}, {%4,%5,%6,%7}, {%8,%9}, {%0,%1,%2,%3};"
        : "+f"(c[0]), "+f"(c[1]), "+f"(c[2]), "+f"(c[3])
        : "r"(a[0]), "r"(a[1]), "r"(a[2]), "r"(a[3]), "r"(b[0]), "r"(b[1]));
}
__device__ __forceinline__ void cpa16(void* dst, const void* src) {
    uint32_t d = (uint32_t)__cvta_generic_to_shared(dst);
    asm volatile("cp.async.cg.shared.global [%0], [%1], 16;" :: "r"(d), "l"(src));
}

__global__ __launch_bounds__(256, 1)
void clifford_hmma_kernel(const float* __restrict__ bias, float* __restrict__ out) {
    extern __shared__ char smem[];

    const int tid = threadIdx.x;
    const int lane = tid & 31;
    const int wid = tid >> 5;           // 0..7
    const int wr = wid >> 2;            // 0..1  (warp row: 64 rows)
    const int wc = wid & 3;             // 0..3  (warp col: 32 cols)
    const int g   = lane >> 2;          // 0..7
    const int tg2 = (lane & 3) * 2;     // 0,2,4,6
    const int bx = blockIdx.x, by = blockIdx.y;

    const size_t rowA0 = (size_t)bx * BM;
    const size_t rowB0 = (size_t)by * BN;

    // cp.async mapping: each thread loads 2 16B chunks per tensor per stage.
    // chunk c in [0,512): row = c>>2, colbytes = (c&3)*16  (= (c&3)*8 elems)
    const int c0 = tid * 2;

    auto load_stage = [&](int kt, int slot) {
        const int k0 = kt * BK;
        char* st = smem + slot * STAGE_BYTES;
        const __nv_bfloat16* gsrc[4] = {g_Ahi, g_Alo, g_Bhi, g_Blo};
        const size_t rbase[4] = {rowA0, rowA0, rowB0, rowB0};
#pragma unroll
        for (int t = 0; t < 4; t++) {
            char* dst = st + t * TENSOR_BYTES;
#pragma unroll
            for (int q = 0; q < 2; q++) {
                int c = c0 + q;
                int r = c >> 2, cb = (c & 3);
                cpa16(dst + r * ROWB + cb * 16,
                      gsrc[t] + (rbase[t] + r) * KDIM + k0 + cb * 8);
            }
        }
        asm volatile("cp.async.commit_group;" ::: "memory");
    };

    float acc[4][4][4];                 // [mi][ni][creg]
#pragma unroll
    for (int mi = 0; mi < 4; mi++)
#pragma unroll
        for (int ni = 0; ni < 4; ni++)
#pragma unroll
            for (int r = 0; r < 4; r++) acc[mi][ni][r] = 0.0f;

    load_stage(0, 0);
    load_stage(1, 1);

    for (int it = 0; it < KT; it++) {
        if (it < KT - 1) asm volatile("cp.async.wait_group 1;" ::: "memory");
        else             asm volatile("cp.async.wait_group 0;" ::: "memory");
        __syncthreads();
        if (it + 2 < KT) load_stage(it + 2, (it + 2) % STAGES);

        const char* st = smem + (it % STAGES) * STAGE_BYTES;
        const char* sAhi = st;
        const char* sAlo = st + TENSOR_BYTES;
        const char* sBhi = st + 2 * TENSOR_BYTES;
        const char* sBlo = st + 3 * TENSOR_BYTES;

#pragma unroll
        for (int kk = 0; kk < BK; kk += 16) {
            uint32_t ah[4][4], al[4][4], bh[4][2], bl[4][2];
#pragma unroll
            for (int mi = 0; mi < 4; mi++) {
                int r0 = wr * 64 + mi * 16 + g;
                const char* p0 = sAhi + r0 * ROWB + (kk + tg2) * 2;
                const char* p1 = sAhi + (r0 + 8) * ROWB + (kk + tg2) * 2;
                ah[mi][0] = *(const uint32_t*)p0;
                ah[mi][1] = *(const uint32_t*)p1;
                ah[mi][2] = *(const uint32_t*)(p0 + 16);
                ah[mi][3] = *(const uint32_t*)(p1 + 16);
                const char* q0 = sAlo + r0 * ROWB + (kk + tg2) * 2;
                const char* q1 = sAlo + (r0 + 8) * ROWB + (kk + tg2) * 2;
                al[mi][0] = *(const uint32_t*)q0;
                al[mi][1] = *(const uint32_t*)q1;
                al[mi][2] = *(const uint32_t*)(q0 + 16);
                al[mi][3] = *(const uint32_t*)(q1 + 16);
            }
#pragma unroll
            for (int ni = 0; ni < 4; ni++) {
                int n0 = wc * 32 + ni * 8 + g;
                const char* p = sBhi + n0 * ROWB + (kk + tg2) * 2;
                bh[ni][0] = *(const uint32_t*)p;
                bh[ni][1] = *(const uint32_t*)(p + 16);
                const char* q = sBlo + n0 * ROWB + (kk + tg2) * 2;
                bl[ni][0] = *(const uint32_t*)q;
                bl[ni][1] = *(const uint32_t*)(q + 16);
            }
#pragma unroll
            for (int mi = 0; mi < 4; mi++)
#pragma unroll
                for (int ni = 0; ni < 4; ni++) {
                    mma_bf16(acc[mi][ni], ah[mi], bh[ni]);
                    mma_bf16(acc[mi][ni], al[mi], bh[ni]);
                    mma_bf16(acc[mi][ni], ah[mi], bl[ni]);
                }
        }
        __syncthreads();
    }

    // epilogue: acc + bias -> out
#pragma unroll
    for (int mi = 0; mi < 4; mi++) {
        int grow0 = bx * BM + wr * 64 + mi * 16 + g;
#pragma unroll
        for (int ni = 0; ni < 4; ni++) {
            int gcol = by * BN + wc * 32 + ni * 8 + tg2;
            float b0 = bias[gcol], b1 = bias[gcol + 1];
            float2 v0 = {acc[mi][ni][0] + b0, acc[mi][ni][1] + b1};
            float2 v1 = {acc[mi][ni][2] + b0, acc[mi][ni][3] + b1};
            *(float2*)(out + (size_t)grow0 * NDIM + gcol) = v0;
            *(float2*)(out + (size_t)(grow0 + 8) * NDIM + gcol) = v1;
        }
    }
}

extern "C" void kernel_launch(void* const* d_in, const int* in_sizes, int n_in,
                              void* d_out, int out_size) {
    const float* x      = (const float*)d_in[0];  // [8192, 256, 8]
    const float* weight = (const float*)d_in[1];  // [256, 256, 8]
    const float* bias   = (const float*)d_in[2];  // [256, 8]
    const float* cayley = (const float*)d_in[3];  // [8, 8, 8]
    float* out = (float*)d_out;
    (void)in_sizes; (void)n_in; (void)out_size;

    cudaFuncSetAttribute(clifford_hmma_kernel,
                         cudaFuncAttributeMaxDynamicSharedMemorySize, SMEM_TOTAL);

    split_x_kernel<<<(BATCH * KDIM / 4) / 256, 256>>>(x);
    build_weff_kernel<<<(NDIM * KDIM) / 256, 256>>>(weight, cayley);

    dim3 grid(BATCH / BM, NDIM / BN);   // (64, 16)
    clifford_hmma_kernel<<<grid, 256, SMEM_TOTAL>>>(bias, out);
}

// round 11
// speedup vs baseline: 4.5017x; 2.4998x over previous
#include <cuda_runtime.h>
#include <cuda_fp16.h>
#include <cstdint>

// CliffordLinear == dense GEMM: out[b,n] = sum_k X[b,k]*Weff[n,k] + bias[n]
//   Weff[o*8+l, i*8+kb] = cayley[kb^l, kb, l] * W[o, i, kb^l]
// Single-pass fp16 HMMA (fp32 accumulate). fp16 quantization gives norm-rel
// error ~4e-4 < 1e-3 threshold (K-independent, random-sign cancellation).

#define NB     8
#define CIN    256
#define BATCH  8192
#define KDIM   2048
#define NDIM   2048

#define BM 128
#define BN 128
#define BK 32
#define KT (KDIM / BK)          // 64 k-tiles
#define STAGES 3

#define ROWB 80                 // 64B data + 16B pad per smem row
#define TENSOR_BYTES (128 * ROWB)               // 10240
#define STAGE_BYTES  (2 * TENSOR_BYTES)         // 20480 (A + B)
#define SMEM_TOTAL   (STAGES * STAGE_BYTES)     // 61440

// ---- scratch (static device arrays; no allocs) ----
__device__ __half g_Ah[(size_t)BATCH * KDIM];
__device__ __half g_Bh[(size_t)NDIM * KDIM];

// ---- conversion kernels ----
__global__ void convert_x_kernel(const float* __restrict__ x) {
    size_t i = (size_t)blockIdx.x * blockDim.x + threadIdx.x;  // float4 index
    float4 v = ((const float4*)x)[i];
    __half2 h01 = __floats2half2_rn(v.x, v.y);
    __half2 h23 = __floats2half2_rn(v.z, v.w);
    ((__half2*)g_Ah)[i * 2 + 0] = h01;
    ((__half2*)g_Ah)[i * 2 + 1] = h23;
}

__global__ void build_weff_kernel(const float* __restrict__ W,
                                  const float* __restrict__ C) {
    int idx = blockIdx.x * blockDim.x + threadIdx.x;  // n*KDIM + k
    int k = idx & (KDIM - 1);
    int n = idx >> 11;
    int kb = k & 7, i = k >> 3;
    int l = n & 7, o = n >> 3;
    int j = kb ^ l;
    float w = C[(j * 8 + kb) * 8 + l] * W[(o * CIN + i) * NB + j];
    g_Bh[idx] = __float2half_rn(w);
}

// ---- mma / cp.async helpers (sm80-level PTX only; compute_103-safe) ----
__device__ __forceinline__ void mma_f16(float* c, const uint32_t* a, const uint32_t* b) {
    asm volatile(
        "mma.sync.aligned.m16n8k16.row.col.f32.f16.f16.f32 "
        "{%0,%1,%2,%3}, {%4,%5,%6,%7}, {%8,%9}, {%0,%1,%2,%3};"
        : "+f"(c[0]), "+f"(c[1]), "+f"(c[2]), "+f"(c[3])
        : "r"(a[0]), "r"(a[1]), "r"(a[2]), "r"(a[3]), "r"(b[0]), "r"(b[1]));
}
__device__ __forceinline__ void cpa16(void* dst, const void* src) {
    uint32_t d = (uint32_t)__cvta_generic_to_shared(dst);
    asm volatile("cp.async.cg.shared.global [%0], [%1], 16;" :: "r"(d), "l"(src));
}

__global__ __launch_bounds__(256, 2)
void clifford_hmma_kernel(const float* __restrict__ bias, float* __restrict__ out) {
    extern __shared__ char smem[];

    const int tid = threadIdx.x;
    const int lane = tid & 31;
    const int wid = tid >> 5;           // 0..7
    const int wr = wid >> 2;            // 0..1  (warp row: 64 rows)
    const int wc = wid & 3;             // 0..3  (warp col: 32 cols)
    const int g   = lane >> 2;          // 0..7
    const int tg2 = (lane & 3) * 2;     // 0,2,4,6
    const int bx = blockIdx.x, by = blockIdx.y;

    const size_t rowA0 = (size_t)bx * BM;
    const size_t rowB0 = (size_t)by * BN;

    // cp.async mapping: each thread loads 2 16B chunks per tensor per stage.
    // chunk c in [0,512): row = c>>2, colbytes = (c&3)*16
    const int c0 = tid * 2;

    auto load_stage = [&](int kt, int slot) {
        const int k0 = kt * BK;
        char* st = smem + slot * STAGE_BYTES;
#pragma unroll
        for (int q = 0; q < 2; q++) {
            int c = c0 + q;
            int r = c >> 2, cb = (c & 3);
            cpa16(st + r * ROWB + cb * 16,
                  g_Ah + (rowA0 + r) * KDIM + k0 + cb * 8);
        }
#pragma unroll
        for (int q = 0; q < 2; q++) {
            int c = c0 + q;
            int r = c >> 2, cb = (c & 3);
            cpa16(st + TENSOR_BYTES + r * ROWB + cb * 16,
                  g_Bh + (rowB0 + r) * KDIM + k0 + cb * 8);
        }
        asm volatile("cp.async.commit_group;" ::: "memory");
    };

    float acc[4][4][4];                 // [mi][ni][creg]
#pragma unroll
    for (int mi = 0; mi < 4; mi++)
#pragma unroll
        for (int ni = 0; ni < 4; ni++)
#pragma unroll
            for (int r = 0; r < 4; r++) acc[mi][ni][r] = 0.0f;

    load_stage(0, 0);
    load_stage(1, 1);

    for (int it = 0; it < KT; it++) {
        if (it < KT - 1) asm volatile("cp.async.wait_group 1;" ::: "memory");
        else             asm volatile("cp.async.wait_group 0;" ::: "memory");
        __syncthreads();
        if (it + 2 < KT) load_stage(it + 2, (it + 2) % STAGES);

        const char* st = smem + (it % STAGES) * STAGE_BYTES;
        const char* sA = st;
        const char* sB = st + TENSOR_BYTES;

#pragma unroll
        for (int kk = 0; kk < BK; kk += 16) {
            uint32_t a[4][4], b[4][2];
#pragma unroll
            for (int mi = 0; mi < 4; mi++) {
                int r0 = wr * 64 + mi * 16 + g;
                const char* p0 = sA + r0 * ROWB + (kk + tg2) * 2;
                const char* p1 = sA + (r0 + 8) * ROWB + (kk + tg2) * 2;
                a[mi][0] = *(const uint32_t*)p0;
                a[mi][1] = *(const uint32_t*)p1;
                a[mi][2] = *(const uint32_t*)(p0 + 16);
                a[mi][3] = *(const uint32_t*)(p1 + 16);
            }
#pragma unroll
            for (int ni = 0; ni < 4; ni++) {
                int n0 = wc * 32 + ni * 8 + g;
                const char* p = sB + n0 * ROWB + (kk + tg2) * 2;
                b[ni][0] = *(const uint32_t*)p;
                b[ni][1] = *(const uint32_t*)(p + 16);
            }
#pragma unroll
            for (int mi = 0; mi < 4; mi++)
#pragma unroll
                for (int ni = 0; ni < 4; ni++)
                    mma_f16(acc[mi][ni], a[mi], b[ni]);
        }
        __syncthreads();
    }

    // epilogue: acc + bias -> out
#pragma unroll
    for (int mi = 0; mi < 4; mi++) {
        int grow0 = bx * BM + wr * 64 + mi * 16 + g;
#pragma unroll
        for (int ni = 0; ni < 4; ni++) {
            int gcol = by * BN + wc * 32 + ni * 8 + tg2;
            float b0 = bias[gcol], b1 = bias[gcol + 1];
            float2 v0 = {acc[mi][ni][0] + b0, acc[mi][ni][1] + b1};
            float2 v1 = {acc[mi][ni][2] + b0, acc[mi][ni][3] + b1};
            *(float2*)(out + (size_t)grow0 * NDIM + gcol) = v0;
            *(float2*)(out + (size_t)(grow0 + 8) * NDIM + gcol) = v1;
        }
    }
}

extern "C" void kernel_launch(void* const* d_in, const int* in_sizes, int n_in,
                              void* d_out, int out_size) {
    const float* x      = (const float*)d_in[0];  // [8192, 256, 8]
    const float* weight = (const float*)d_in[1];  // [256, 256, 8]
    const float* bias   = (const float*)d_in[2];  // [256, 8]
    const float* cayley = (const float*)d_in[3];  // [8, 8, 8]
    float* out = (float*)d_out;
    (void)in_sizes; (void)n_in; (void)out_size;

    cudaFuncSetAttribute(clifford_hmma_kernel,
                         cudaFuncAttributeMaxDynamicSharedMemorySize, SMEM_TOTAL);

    convert_x_kernel<<<(BATCH * KDIM / 4) / 256, 256>>>(x);
    build_weff_kernel<<<(NDIM * KDIM) / 256, 256>>>(weight, cayley);

    dim3 grid(BATCH / BM, NDIM / BN);   // (64, 16)
    clifford_hmma_kernel<<<grid, 256, SMEM_TOTAL>>>(bias, out);
}